// round 5
// baseline (speedup 1.0000x reference)
#include <cuda_runtime.h>
#include <cuda_bf16.h>
#include <math.h>

// ConvLSTM via tensor cores (mma.sync m16n8k16 bf16, 3-term hi/lo split).
// Round 5: each warp covers 32 pixels (2 m16 tiles) -> B-fragment LDSM
// traffic per MMA halves (1.0 wf/MMA); block = 4 rows x 64 x 64 oc, occ 1.
// x: (8,16,64,64,64) f32, Wk: (256,128,3,3) f32
// out: [hid | cell], each 8*64*64*64 f32 (NCHW).

#define HW 64

__device__ __nv_bfloat16 g_xs[2][8][16][HW][HW][64];   // x, channel-last hi/lo
__device__ __nv_bfloat16 g_hs[2][2][8][HW][HW][64];    // [parity][split] h hi/lo
__device__ __nv_bfloat16 g_wb[2][9][256][128];         // weights [sp][tap][oc][ic]

// ---------------- prep kernels ----------------

__global__ void prep_w(const float* __restrict__ Wk)
{
    int i = blockIdx.x * blockDim.x + threadIdx.x;   // over 256*128*9
    if (i >= 256 * 128 * 9) return;
    int tap = i % 9;
    int ic  = (i / 9) % 128;
    int oc  = i / (9 * 128);
    float v = Wk[(size_t)(oc * 128 + ic) * 9 + tap];
    __nv_bfloat16 hi = __float2bfloat16(v);
    float lo = v - __bfloat162float(hi);
    g_wb[0][tap][oc][ic] = hi;
    g_wb[1][tap][oc][ic] = __float2bfloat16(lo);
}

__global__ void prep_x(const float* __restrict__ x)
{
    __shared__ float tile[64][65];
    int y  = blockIdx.x & 63;
    int bt = blockIdx.x >> 6;               // b*16 + t
    const float* src = x + (size_t)bt * 64 * 4096 + y * 64;
    for (int i = threadIdx.x; i < 64 * 64; i += 256) {
        int ic = i >> 6, xx = i & 63;
        tile[ic][xx] = src[ic * 4096 + xx];
    }
    __syncthreads();
    int b = bt >> 4, t = bt & 15;
    for (int i = threadIdx.x; i < 64 * 64; i += 256) {
        int xx = i >> 6, ic = i & 63;
        float v = tile[ic][xx];
        __nv_bfloat16 hi = __float2bfloat16(v);
        g_xs[0][b][t][y][xx][ic] = hi;
        g_xs[1][b][t][y][xx][ic] = __float2bfloat16(v - __bfloat162float(hi));
    }
}

// ---------------- mma helpers ----------------

__device__ __forceinline__ void ldsm4(unsigned &r0, unsigned &r1,
                                      unsigned &r2, unsigned &r3, unsigned a)
{
    asm volatile("ldmatrix.sync.aligned.m8n8.x4.shared.b16 {%0,%1,%2,%3}, [%4];"
                 : "=r"(r0), "=r"(r1), "=r"(r2), "=r"(r3) : "r"(a));
}

__device__ __forceinline__ void mma_bf16(float* c, const unsigned* a, const unsigned* b)
{
    asm volatile("mma.sync.aligned.m16n8k16.row.col.f32.bf16.bf16.f32 "
                 "{%0,%1,%2,%3},{%4,%5,%6,%7},{%8,%9},{%0,%1,%2,%3};"
                 : "+f"(c[0]), "+f"(c[1]), "+f"(c[2]), "+f"(c[3])
                 : "r"(a[0]), "r"(a[1]), "r"(a[2]), "r"(a[3]),
                   "r"(b[0]), "r"(b[1]));
}

// smem (bf16 elems): s_in [2][6][66][24] = 19008 ; s_w [2][9][64][24] = 27648
#define SIN_ELEMS 19008
#define SIN_SP    (6 * 66 * 24)
#define SMEM_BYTES ((19008 + 27648) * 2)

__global__ __launch_bounds__(256, 1)
void convlstm_mma(float* __restrict__ hid_out, float* __restrict__ cell_io,
                  int t, int last)
{
    extern __shared__ __nv_bfloat16 smem[];
    __nv_bfloat16* s_in = smem;               // [sp][sy 6][sx 66][ic 24-pad]
    __nv_bfloat16* s_w  = smem + SIN_ELEMS;   // [sp][tap 9][ocl 64][ic 24-pad]

    const int tid  = threadIdx.x;
    const int w    = tid >> 5;
    const int lane = tid & 31;
    const int y0   = blockIdx.x * 4;      // 4 output rows per block
    const int hcg  = blockIdx.y;          // hidden-ch group (16 each)
    const int b    = blockIdx.z;

    const int par_in  = t & 1;
    const int par_out = (t + 1) & 1;

    const unsigned sIn = (unsigned)__cvta_generic_to_shared(s_in);
    const unsigned sW  = (unsigned)__cvta_generic_to_shared(s_w);

    // lane-invariant ldmatrix offsets
    const int t4 = lane >> 3, r8 = lane & 7;
    const int prA = ((t4 & 1) << 3) + r8;       // row within m16
    const int k8A = t4 >> 1;                    // k-half
    unsigned laneA[2];
#pragma unroll
    for (int mt = 0; mt < 2; mt++) {
        const int p0  = w * 32 + mt * 16 + prA;
        const int pyA = p0 >> 6;                // 0..3 local output row
        const int pxA = p0 & 63;
        laneA[mt] = (unsigned)((pyA * 66 + pxA) * 24 + 8 * k8A) * 2u;
    }
    const int hi8 = (t4 >= 2) ? 8 : 0;
    const unsigned laneB = (unsigned)(((hi8 + r8) * 24) + 8 * (t4 & 1)) * 2u;

    float acc[2][8][4];
#pragma unroll
    for (int m = 0; m < 2; m++)
#pragma unroll
        for (int i = 0; i < 8; i++)
#pragma unroll
            for (int j = 0; j < 4; j++) acc[m][i][j] = 0.f;

    const int nkb = (t == 0) ? 4 : 8;    // 16-ch blocks: 4 x-src (+4 h-src)

    for (int kb = 0; kb < nkb; kb++) {
        __syncthreads();
        // stage input tile (2 splits, 6 y-rows with halo, 66 x, 16 ic)
        for (int c = tid; c < 1584; c += 256) {
            int sp   = c / 792;
            int idx  = c - sp * 792;
            int pix  = idx >> 1, half = idx & 1;
            int sy   = pix / 66, sx = pix - sy * 66;
            int gy   = y0 - 1 + sy, gx = sx - 1;
            uint4 v  = make_uint4(0u, 0u, 0u, 0u);
            if ((unsigned)gy < 64u && (unsigned)gx < 64u) {
                const __nv_bfloat16* src = (kb < 4)
                    ? &g_xs[sp][b][t][gy][gx][kb * 16 + half * 8]
                    : &g_hs[par_in][sp][b][gy][gx][(kb - 4) * 16 + half * 8];
                v = *(const uint4*)src;
            }
            *(uint4*)&s_in[((sp * 6 + sy) * 66 + sx) * 24 + half * 8] = v;
        }
        // stage weights for this ic-block, all 9 taps, both splits
        for (int c = tid; c < 2304; c += 256) {
            int sp   = c / 1152;
            int idx  = c - sp * 1152;
            int tap  = idx >> 7;
            int r    = idx & 127;
            int ocl  = r >> 1, half = r & 1;
            int oc   = (ocl >> 4) * 64 + hcg * 16 + (ocl & 15); // gate*64 + hc
            uint4 v  = *(const uint4*)&g_wb[sp][tap][oc][kb * 16 + half * 8];
            *(uint4*)&s_w[((sp * 9 + tap) * 64 + ocl) * 24 + half * 8] = v;
        }
        __syncthreads();

#pragma unroll 1
        for (int tap = 0; tap < 9; tap++) {
            const int dyp = tap / 3, dxp = tap - dyp * 3;
            const unsigned aoff = (unsigned)((dyp * 66 + dxp) * 24) * 2u;

            unsigned a[2][2][4];   // [mt][sp][frag]
#pragma unroll
            for (int mt = 0; mt < 2; mt++) {
                ldsm4(a[mt][0][0], a[mt][0][1], a[mt][0][2], a[mt][0][3],
                      sIn + aoff + laneA[mt]);
                ldsm4(a[mt][1][0], a[mt][1][1], a[mt][1][2], a[mt][1][3],
                      sIn + (unsigned)(SIN_SP * 2) + aoff + laneA[mt]);
            }

            unsigned bf[2][8][2];
#pragma unroll
            for (int sp = 0; sp < 2; sp++) {
                unsigned base = sW + (unsigned)((sp * 9 + tap) * 64 * 24) * 2u + laneB;
#pragma unroll
                for (int j = 0; j < 4; j++) {
                    ldsm4(bf[sp][2 * j][0], bf[sp][2 * j][1],
                          bf[sp][2 * j + 1][0], bf[sp][2 * j + 1][1],
                          base + (unsigned)(16 * j * 24) * 2u);
                }
            }
#pragma unroll
            for (int nf = 0; nf < 8; nf++) {
#pragma unroll
                for (int mt = 0; mt < 2; mt++) {
                    mma_bf16(acc[mt][nf], a[mt][0], bf[0][nf]);   // hi*hi
                    mma_bf16(acc[mt][nf], a[mt][0], bf[1][nf]);   // hi*w_lo
                    mma_bf16(acc[mt][nf], a[mt][1], bf[0][nf]);   // lo*w_hi
                }
            }
        }
    }

    // ---- fused LSTM epilogue ----
    const int c0    = (lane & 3) * 2;
    const int rbase = lane >> 2;
#pragma unroll
    for (int mt = 0; mt < 2; mt++) {
#pragma unroll
        for (int rr = 0; rr < 2; rr++) {
            const int pe = w * 32 + mt * 16 + rbase + 8 * rr;
            const int y  = y0 + (pe >> 6);
            const int x  = pe & 63;
#pragma unroll
            for (int q = 0; q < 4; q++) {
                const int hcl  = c0 + (q & 1) + ((q >> 1) << 3);
                const int off  = (hcl >= 8) ? 1 : 0;
                const int cidx = (hcl & 7) - c0 + rr * 2;
                float vi = acc[mt][0 + off][cidx];
                float vf = acc[mt][2 + off][cidx];
                float vo = acc[mt][4 + off][cidx];
                float vg = acc[mt][6 + off][cidx];
                float iv = 1.f / (1.f + __expf(-vi));
                float fv = 1.f / (1.f + __expf(-vf));
                float ov = 1.f / (1.f + __expf(-vo));
                float gv = tanhf(vg);
                const int hc = hcg * 16 + hcl;
                const size_t addr = (((size_t)b * 64 + hc) * 64 + y) * 64 + x;
                float cold = (t == 0) ? 0.f : cell_io[addr];
                float cnew = fv * cold + iv * gv;
                cell_io[addr] = cnew;
                float hval = ov * tanhf(cnew);
                if (last) {
                    hid_out[addr] = hval;
                } else {
                    __nv_bfloat16 hh = __float2bfloat16(hval);
                    g_hs[par_out][0][b][y][x][hc] = hh;
                    g_hs[par_out][1][b][y][x][hc] =
                        __float2bfloat16(hval - __bfloat162float(hh));
                }
            }
        }
    }
}

extern "C" void kernel_launch(void* const* d_in, const int* in_sizes, int n_in,
                              void* d_out, int out_size)
{
    const float* x  = (const float*)d_in[0];
    const float* Wk = (const float*)d_in[1];
    float* out  = (float*)d_out;
    float* hid  = out;
    float* cell = out + out_size / 2;

    cudaFuncSetAttribute(convlstm_mma,
                         cudaFuncAttributeMaxDynamicSharedMemorySize, SMEM_BYTES);

    prep_w<<<(256 * 128 * 9 + 255) / 256, 256>>>(Wk);
    prep_x<<<8 * 16 * 64, 256>>>(x);

    dim3 grid(16, 4, 8), blk(256);
    for (int t = 0; t < 16; t++)
        convlstm_mma<<<grid, blk, SMEM_BYTES>>>(hid, cell, t, t == 15 ? 1 : 0);
}

// round 7
// speedup vs baseline: 1.1579x; 1.1579x over previous
#include <cuda_runtime.h>
#include <cuda_bf16.h>
#include <math.h>

// ConvLSTM via mma.sync m16n8k16 bf16, 3-term hi/lo split.
// Round 7: CTA = 128 pixels (2 rows x 64) x 64 oc, but only 4 warps;
// each warp covers 2 m16 tiles -> B-fragment LDSM traffic per MMA halves
// while 2 CTAs/SM keep staging/compute overlap. cp.async staging.
// x: (8,16,64,64,64) f32, Wk: (256,128,3,3) f32
// out: [hid | cell], each 8*64*64*64 f32 (NCHW).

#define HW 64

__device__ __nv_bfloat16 g_xs[2][8][16][HW][HW][64];   // x channel-last hi/lo
__device__ __nv_bfloat16 g_hs[2][2][8][HW][HW][64];    // [parity][split] h hi/lo
__device__ __nv_bfloat16 g_wb[2][9][256][128];         // weights [sp][tap][oc][ic]
__device__ __align__(16) __nv_bfloat16 g_zero16[8] = {};

// ---------------- prep kernels ----------------

__global__ void prep_w(const float* __restrict__ Wk)
{
    int i = blockIdx.x * blockDim.x + threadIdx.x;
    if (i >= 256 * 128 * 9) return;
    int tap = i % 9;
    int ic  = (i / 9) % 128;
    int oc  = i / (9 * 128);
    float v = Wk[(size_t)(oc * 128 + ic) * 9 + tap];
    __nv_bfloat16 hi = __float2bfloat16(v);
    float lo = v - __bfloat162float(hi);
    g_wb[0][tap][oc][ic] = hi;
    g_wb[1][tap][oc][ic] = __float2bfloat16(lo);
}

__global__ void prep_x(const float* __restrict__ x)
{
    __shared__ float tile[64][65];
    int y  = blockIdx.x & 63;
    int bt = blockIdx.x >> 6;               // b*16 + t
    const float* src = x + (size_t)bt * 64 * 4096 + y * 64;
    for (int i = threadIdx.x; i < 64 * 64; i += 256) {
        int ic = i >> 6, xx = i & 63;
        tile[ic][xx] = src[ic * 4096 + xx];
    }
    __syncthreads();
    int b = bt >> 4, t = bt & 15;
    for (int i = threadIdx.x; i < 64 * 64; i += 256) {
        int xx = i >> 6, ic = i & 63;
        float v = tile[ic][xx];
        __nv_bfloat16 hi = __float2bfloat16(v);
        g_xs[0][b][t][y][xx][ic] = hi;
        g_xs[1][b][t][y][xx][ic] = __float2bfloat16(v - __bfloat162float(hi));
    }
}

// ---------------- helpers ----------------

__device__ __forceinline__ void ldsm4(unsigned &r0, unsigned &r1,
                                      unsigned &r2, unsigned &r3, unsigned a)
{
    asm volatile("ldmatrix.sync.aligned.m8n8.x4.shared.b16 {%0,%1,%2,%3}, [%4];"
                 : "=r"(r0), "=r"(r1), "=r"(r2), "=r"(r3) : "r"(a));
}

__device__ __forceinline__ void mma_bf16(float* c, const unsigned* a, const unsigned* b)
{
    asm volatile("mma.sync.aligned.m16n8k16.row.col.f32.bf16.bf16.f32 "
                 "{%0,%1,%2,%3},{%4,%5,%6,%7},{%8,%9},{%0,%1,%2,%3};"
                 : "+f"(c[0]), "+f"(c[1]), "+f"(c[2]), "+f"(c[3])
                 : "r"(a[0]), "r"(a[1]), "r"(a[2]), "r"(a[3]),
                   "r"(b[0]), "r"(b[1]));
}

__device__ __forceinline__ void cpasync16(unsigned dst, const void* src)
{
    asm volatile("cp.async.cg.shared.global [%0], [%1], 16;"
                 :: "r"(dst), "l"(src) : "memory");
}

// smem (bf16 elems): s_in [2][4][66][24] = 12672 ; s_w [2][9][64][24] = 27648
#define SIN_ELEMS 12672
#define SIN_SP    (4 * 66 * 24)
#define SMEM_BYTES ((12672 + 27648) * 2)

__global__ __launch_bounds__(128, 2)
void convlstm_mma(float* __restrict__ hid_out, float* __restrict__ cell_io,
                  int t, int last)
{
    extern __shared__ __nv_bfloat16 smem[];
    __nv_bfloat16* s_in = smem;               // [sp][sy 4][sx 66][ic 24-pad]
    __nv_bfloat16* s_w  = smem + SIN_ELEMS;   // [sp][tap 9][ocl 64][ic 24-pad]

    const int tid  = threadIdx.x;
    const int w    = tid >> 5;            // 0..3
    const int lane = tid & 31;
    const int y0   = blockIdx.x * 2;      // 2 output rows per block
    const int hcg  = blockIdx.y;          // hidden-ch group (16 each)
    const int b    = blockIdx.z;

    const int par_in  = t & 1;
    const int par_out = (t + 1) & 1;

    const unsigned sIn = (unsigned)__cvta_generic_to_shared(s_in);
    const unsigned sW  = (unsigned)__cvta_generic_to_shared(s_w);

    // lane-invariant ldmatrix offsets
    const int t4 = lane >> 3, r8 = lane & 7;
    const int prA = ((t4 & 1) << 3) + r8;       // row within m16
    const int k8A = t4 >> 1;                    // k-half
    unsigned laneA[2];
#pragma unroll
    for (int mt = 0; mt < 2; mt++) {
        const int p0  = w * 32 + mt * 16 + prA;   // 0..127
        const int pyA = p0 >> 6;                  // 0/1 local row
        const int pxA = p0 & 63;
        laneA[mt] = (unsigned)((pyA * 66 + pxA) * 24 + 8 * k8A) * 2u;
    }
    const int hi8 = (t4 >= 2) ? 8 : 0;
    const unsigned laneB = (unsigned)(((hi8 + r8) * 24) + 8 * (t4 & 1)) * 2u;

    float acc[2][8][4];
#pragma unroll
    for (int m = 0; m < 2; m++)
#pragma unroll
        for (int i = 0; i < 8; i++)
#pragma unroll
            for (int j = 0; j < 4; j++) acc[m][i][j] = 0.f;

    const int nkb = (t == 0) ? 4 : 8;    // 16-ch blocks: 4 x-src (+4 h-src)

    for (int kb = 0; kb < nkb; kb++) {
        __syncthreads();   // previous kb's ldsm reads complete

        // ---- stage input tile via cp.async (2 sp, 4 rows w/ halo, 66 x, 16 ic)
        for (int c = tid; c < 1056; c += 128) {
            int sp   = c / 528;
            int idx  = c - sp * 528;
            int pix  = idx >> 1, half = idx & 1;
            int sy   = pix / 66, sx = pix - sy * 66;
            int gy   = y0 - 1 + sy, gx = sx - 1;
            const void* src = g_zero16;
            if ((unsigned)gy < 64u && (unsigned)gx < 64u)
                src = (kb < 4)
                    ? (const void*)&g_xs[sp][b][t][gy][gx][kb * 16 + half * 8]
                    : (const void*)&g_hs[par_in][sp][b][gy][gx][(kb - 4) * 16 + half * 8];
            unsigned dst = sIn + (unsigned)(((sp * 4 + sy) * 66 + sx) * 24 + half * 8) * 2u;
            cpasync16(dst, src);
        }
        // ---- stage weights via cp.async (this ic-block, 9 taps, both splits)
        for (int c = tid; c < 2304; c += 128) {
            int sp   = c / 1152;
            int idx  = c - sp * 1152;
            int tap  = idx >> 7;
            int r    = idx & 127;
            int ocl  = r >> 1, half = r & 1;
            int oc   = (ocl >> 4) * 64 + hcg * 16 + (ocl & 15); // gate*64 + hc
            unsigned dst = sW + (unsigned)(((sp * 9 + tap) * 64 + ocl) * 24 + half * 8) * 2u;
            cpasync16(dst, &g_wb[sp][tap][oc][kb * 16 + half * 8]);
        }
        asm volatile("cp.async.commit_group;" ::: "memory");
        asm volatile("cp.async.wait_group 0;" ::: "memory");
        __syncthreads();

#pragma unroll 1
        for (int tap = 0; tap < 9; tap++) {
            const int dyp = tap / 3, dxp = tap - dyp * 3;
            const unsigned aoff = (unsigned)((dyp * 66 + dxp) * 24) * 2u;

            unsigned a[2][2][4];   // [mt][sp][frag]
#pragma unroll
            for (int mt = 0; mt < 2; mt++) {
                ldsm4(a[mt][0][0], a[mt][0][1], a[mt][0][2], a[mt][0][3],
                      sIn + aoff + laneA[mt]);
                ldsm4(a[mt][1][0], a[mt][1][1], a[mt][1][2], a[mt][1][3],
                      sIn + (unsigned)(SIN_SP * 2) + aoff + laneA[mt]);
            }

            unsigned bf[2][8][2];
#pragma unroll
            for (int sp = 0; sp < 2; sp++) {
                unsigned base = sW + (unsigned)((sp * 9 + tap) * 64 * 24) * 2u + laneB;
#pragma unroll
                for (int j = 0; j < 4; j++) {
                    ldsm4(bf[sp][2 * j][0], bf[sp][2 * j][1],
                          bf[sp][2 * j + 1][0], bf[sp][2 * j + 1][1],
                          base + (unsigned)(16 * j * 24) * 2u);
                }
            }
#pragma unroll
            for (int nf = 0; nf < 8; nf++) {
#pragma unroll
                for (int mt = 0; mt < 2; mt++) {
                    mma_bf16(acc[mt][nf], a[mt][0], bf[0][nf]);   // hi*hi
                    mma_bf16(acc[mt][nf], a[mt][0], bf[1][nf]);   // hi*w_lo
                    mma_bf16(acc[mt][nf], a[mt][1], bf[0][nf]);   // lo*w_hi
                }
            }
        }
    }

    // ---- fused LSTM epilogue ----
    const int c0    = (lane & 3) * 2;
    const int rbase = lane >> 2;
#pragma unroll
    for (int mt = 0; mt < 2; mt++) {
#pragma unroll
        for (int rr = 0; rr < 2; rr++) {
            const int pe = w * 32 + mt * 16 + rbase + 8 * rr;
            const int y  = y0 + (pe >> 6);
            const int x  = pe & 63;
#pragma unroll
            for (int q = 0; q < 4; q++) {
                const int hcl  = c0 + (q & 1) + ((q >> 1) << 3);
                const int off  = (hcl >= 8) ? 1 : 0;
                const int cidx = (hcl & 7) - c0 + rr * 2;
                float vi = acc[mt][0 + off][cidx];
                float vf = acc[mt][2 + off][cidx];
                float vo = acc[mt][4 + off][cidx];
                float vg = acc[mt][6 + off][cidx];
                float iv = 1.f / (1.f + __expf(-vi));
                float fv = 1.f / (1.f + __expf(-vf));
                float ov = 1.f / (1.f + __expf(-vo));
                float gv = tanhf(vg);
                const int hc = hcg * 16 + hcl;
                const size_t addr = (((size_t)b * 64 + hc) * 64 + y) * 64 + x;
                float cold = (t == 0) ? 0.f : cell_io[addr];
                float cnew = fv * cold + iv * gv;
                cell_io[addr] = cnew;
                float hval = ov * tanhf(cnew);
                if (last) {
                    hid_out[addr] = hval;
                } else {
                    __nv_bfloat16 hh = __float2bfloat16(hval);
                    g_hs[par_out][0][b][y][x][hc] = hh;
                    g_hs[par_out][1][b][y][x][hc] =
                        __float2bfloat16(hval - __bfloat162float(hh));
                }
            }
        }
    }
}

extern "C" void kernel_launch(void* const* d_in, const int* in_sizes, int n_in,
                              void* d_out, int out_size)
{
    const float* x  = (const float*)d_in[0];
    const float* Wk = (const float*)d_in[1];
    float* out  = (float*)d_out;
    float* hid  = out;
    float* cell = out + out_size / 2;

    cudaFuncSetAttribute(convlstm_mma,
                         cudaFuncAttributeMaxDynamicSharedMemorySize, SMEM_BYTES);

    prep_w<<<(256 * 128 * 9 + 255) / 256, 256>>>(Wk);
    prep_x<<<8 * 16 * 64, 256>>>(x);

    dim3 grid(32, 4, 8), blk(128);
    for (int t = 0; t < 16; t++)
        convlstm_mma<<<grid, blk, SMEM_BYTES>>>(hid, cell, t, t == 15 ? 1 : 0);
}